// round 16
// baseline (speedup 1.0000x reference)
#include <cuda_runtime.h>
#include <cuda_fp16.h>
#include <cstdint>

// ---------------------------------------------------------------------------
// MoE forward, Round 15: R14 + (a) Wo fp32->fp16 conversion moved into extra
// grid-z blocks of ffn1 (overlaps DRAM streaming with tensor-bound GEMM;
// ffn2 ordering guarantees completion), (b) compact_kernel 2 float4/thread.
// ---------------------------------------------------------------------------

#define T_TOK   8192
#define D_DIM   768
#define F_DIM   3072
#define E_NUM   8
#define CAP     2560
#define MAXROWS 16384
#define MAXR_PAD 16512

// ---- device scratch -------------------------------------------------------
__device__ int   g_topk_idx[T_TOK * 2];
__device__ float g_topk_w  [T_TOK * 2];
__device__ int   g_tok [MAXROWS];
__device__ float g_wt  [MAXROWS];
__device__ int   g_cnt [E_NUM];
__device__ int   g_base[E_NUM];
__device__ int   g_total;
__device__ float g_P   [E_NUM];
__device__ float g_f   [E_NUM];
__device__ float g_z;

__device__ __half g_Ah [(size_t)MAXR_PAD * D_DIM];
__device__ __half g_Wgh[(size_t)E_NUM * F_DIM * D_DIM];
__device__ __half g_Wuh[(size_t)E_NUM * F_DIM * D_DIM];
__device__ __half g_Woh[(size_t)E_NUM * D_DIM * F_DIM];
__device__ __half g_Hh [(size_t)MAXR_PAD * F_DIM];

// ---- helpers --------------------------------------------------------------
__device__ __forceinline__ uint32_t smem_u32(const void* p) {
    uint32_t a;
    asm("{ .reg .u64 t; cvta.to.shared.u64 t, %1; cvt.u32.u64 %0, t; }"
        : "=r"(a) : "l"(p));
    return a;
}
__device__ __forceinline__ uint32_t pack2h(__half a, __half b) {
    return (uint32_t)__half_as_ushort(a) | ((uint32_t)__half_as_ushort(b) << 16);
}
__device__ __forceinline__ float silu_f(float g) {
    return g / (1.f + __expf(-g));
}
__device__ __forceinline__ void red2(float* p, float a, float b) {
    asm volatile("red.global.add.v2.f32 [%0], {%1, %2};"
                 :: "l"(p), "f"(a), "f"(b) : "memory");
}

#define CP16(d, s)  asm volatile("cp.async.cg.shared.global [%0], [%1], 16;" :: "r"(d), "l"(s))
#define CPCOMMIT()  asm volatile("cp.async.commit_group;" ::: "memory")
#define CPWAIT(n)   asm volatile("cp.async.wait_group %0;" :: "n"(n) : "memory")

#define MMAH(d, a, b)                                                           \
    asm volatile("mma.sync.aligned.m16n8k16.row.col.f32.f16.f16.f32 "          \
        "{%0,%1,%2,%3}, {%4,%5,%6,%7}, {%8,%9}, {%0,%1,%2,%3};"                \
        : "+f"((d)[0]), "+f"((d)[1]), "+f"((d)[2]), "+f"((d)[3])               \
        : "r"((a)[0]), "r"((a)[1]), "r"((a)[2]), "r"((a)[3]),                  \
          "r"((b)[0]), "r"((b)[1]))

#define LDSM4(r0, r1, r2, r3, ad)                                               \
    asm volatile("ldmatrix.sync.aligned.m8n8.x4.shared.b16 {%0,%1,%2,%3}, [%4];" \
        : "=r"(r0), "=r"(r1), "=r"(r2), "=r"(r3) : "r"(ad))

#define STR   80                  // smem row stride bytes (32 fp16 + 8 pad)
#define MATB  (128 * STR)         // 10240 B per 128x32 matrix
#define HMATB (64 * STR)          // 5120 B per 64x32 matrix
#define STG1  (MATB + 2 * HMATB)  // 20480 (Ah 128r, Gh 64r, Uh 64r)
#define STG2  (2 * MATB)          // 20480 (Hh, Bh)

// ffn1 stage loader: A 128x32 + G 64x32 + U 64x32
__device__ __forceinline__ void stage_load1(uint32_t s0, int tid,
    const __half* pA, const __half* pG, const __half* pU, int k0)
{
#pragma unroll
    for (int it = 0; it < 4; it++) {
        int idx = tid + it * 256;
        uint32_t d; const __half* s;
        if (idx < 512)      { int r = idx >> 2,        j = idx & 3;
            d = s0 + r * STR + j * 16;          s = pA + (size_t)r * D_DIM + k0 + j * 8; }
        else if (idx < 768) { int q = idx - 512; int r = q >> 2, j = q & 3;
            d = s0 + MATB + r * STR + j * 16;   s = pG + (size_t)r * D_DIM + k0 + j * 8; }
        else                { int q = idx - 768; int r = q >> 2, j = q & 3;
            d = s0 + MATB + HMATB + r * STR + j * 16;
                                                 s = pU + (size_t)r * D_DIM + k0 + j * 8; }
        CP16(d, s);
    }
    CPCOMMIT();
}

// ffn2 stage loader: 2 matrices of 128x32
__device__ __forceinline__ void stage_load2(uint32_t s0, int tid,
    const __half* pA, const __half* pB, int k0, int rs)
{
#pragma unroll
    for (int it = 0; it < 4; it++) {
        int idx = tid + it * 256;
        uint32_t d; const __half* s;
        if (idx < 512) { int r = idx >> 2, j = idx & 3;
            d = s0 + r * STR + j * 16;        s = pA + (size_t)r * rs + k0 + j * 8; }
        else           { int q = idx - 512; int r = q >> 2, j = q & 3;
            d = s0 + MATB + r * STR + j * 16; s = pB + (size_t)r * rs + k0 + j * 8; }
        CP16(d, s);
    }
    CPCOMMIT();
}

// ---------------------------------------------------------------------------
__global__ void init_kernel() {
    int t = threadIdx.x;
    if (t < E_NUM) { g_P[t] = 0.f; g_f[t] = 0.f; }
    if (t == 0) g_z = 0.f;
}

// ---------------------------------------------------------------------------
// Fused router + gate/up weight-convert kernel. Grid 16384 x 128 threads.
// Blocks with (bid & 7) == 0: router for 4 tokens. Others: grid-stride
// conversion of Wg and Wu only (2 * n4 float4). Wo converts inside ffn1.
// ---------------------------------------------------------------------------
__global__ __launch_bounds__(128) void router_conv_kernel(
    const float* __restrict__ x, const float* __restrict__ w_gate,
    const float* __restrict__ wg, const float* __restrict__ wu, int n4)
{
    int bid = blockIdx.x;

    if ((bid & 7) == 0) {
        // ---- router role -------------------------------------------------
        int warp = threadIdx.x >> 5, lane = threadIdx.x & 31;
        int t = (bid >> 3) * 4 + warp;
        if (t >= T_TOK) return;

        const float* xr = x + (size_t)t * D_DIM;
        float a[24];
#pragma unroll
        for (int i = 0; i < 24; i++) a[i] = xr[i * 32 + lane];

        float logits[E_NUM];
#pragma unroll
        for (int e = 0; e < E_NUM; e++) {
            const float* w = w_gate + (size_t)e * D_DIM;
            float s = 0.f;
#pragma unroll
            for (int i = 0; i < 24; i++) s += a[i] * w[i * 32 + lane];
#pragma unroll
            for (int o = 16; o; o >>= 1) s += __shfl_xor_sync(0xffffffffu, s, o);
            logits[e] = s;
        }

        if (lane == 0) {
            float mx = logits[0];
#pragma unroll
            for (int e = 1; e < E_NUM; e++) mx = fmaxf(mx, logits[e]);
            float pe[E_NUM], se = 0.f;
#pragma unroll
            for (int e = 0; e < E_NUM; e++) { pe[e] = expf(logits[e] - mx); se += pe[e]; }
            float inv = 1.f / se;

            int i0 = 0; float p0 = pe[0];
#pragma unroll
            for (int e = 1; e < E_NUM; e++) if (pe[e] > p0) { p0 = pe[e]; i0 = e; }
            int i1 = -1; float p1 = -1.f;
#pragma unroll
            for (int e = 0; e < E_NUM; e++) if (e != i0 && pe[e] > p1) { p1 = pe[e]; i1 = e; }

            float q0 = p0 * inv, q1 = p1 * inv;
            float sn = 1.f / (q0 + q1);
            g_topk_idx[t * 2 + 0] = i0;
            g_topk_idx[t * 2 + 1] = i1;
            g_topk_w  [t * 2 + 0] = q0 * sn;
            g_topk_w  [t * 2 + 1] = q1 * sn;

            float lse = mx + logf(se);
            atomicAdd(&g_z, lse * lse);
#pragma unroll
            for (int e = 0; e < E_NUM; e++) atomicAdd(&g_P[e], pe[e] * inv);
            atomicAdd(&g_f[i0], 1.f);
            atomicAdd(&g_f[i1], 1.f);
        }
    } else {
        // ---- gate/up weight conversion role -----------------------------
        int crank = bid - (bid >> 3) - 1;              // 0 .. 14335
        const int total  = 2 * n4;
        const int stride = 14336 * 128;
        for (int i = crank * 128 + threadIdx.x; i < total; i += stride) {
            const float* src;
            __half* dst;
            int j = i;
            if (i < n4) { src = wg; dst = g_Wgh; }
            else        { src = wu; dst = g_Wuh; j = i - n4; }
            float4 v = ((const float4*)src)[j];
            uint2 ph = make_uint2(pack2h(__float2half_rn(v.x), __float2half_rn(v.y)),
                                  pack2h(__float2half_rn(v.z), __float2half_rn(v.w)));
            *(uint2*)(dst + (size_t)j * 4) = ph;
        }
    }
}

// ---------------------------------------------------------------------------
// Block-parallel dispatch scan (1024 thr, packed 16-stream prefix sum).
// ---------------------------------------------------------------------------
__global__ __launch_bounds__(1024) void scan_kernel()
{
    __shared__ uint32_t wsum[32][8];
    __shared__ unsigned short ex16s[1024 * 16];   // 32 KB
    __shared__ int sbase[16];
    __shared__ int totS[16];

    int tid = threadIdx.x, lane = tid & 31, warp = tid >> 5;

    const int2* gidx = (const int2*)g_topk_idx;
    int2 idx[8];
    unsigned long long c4 = 0ull;
#pragma unroll
    for (int i = 0; i < 8; i++) {
        idx[i] = gidx[tid * 8 + i];
        c4 += 1ull << (idx[i].x * 4);
        c4 += 1ull << ((8 + idx[i].y) * 4);
    }

    uint32_t pc[8], inc[8];
#pragma unroll
    for (int r = 0; r < 8; r++) {
        uint32_t lo = (uint32_t)((c4 >> (r * 8)) & 0xF);
        uint32_t hi = (uint32_t)((c4 >> (r * 8 + 4)) & 0xF);
        pc[r] = lo | (hi << 16);
        inc[r] = pc[r];
    }

    for (int off = 1; off < 32; off <<= 1) {
#pragma unroll
        for (int r = 0; r < 8; r++) {
            uint32_t v = __shfl_up_sync(0xffffffffu, inc[r], off);
            if (lane >= off) inc[r] += v;
        }
    }
    if (lane == 31)
#pragma unroll
        for (int r = 0; r < 8; r++) wsum[warp][r] = inc[r];
    __syncthreads();

    if (warp == 0) {
        uint32_t w0[8], wi[8];
#pragma unroll
        for (int r = 0; r < 8; r++) { w0[r] = wsum[lane][r]; wi[r] = w0[r]; }
        for (int off = 1; off < 32; off <<= 1) {
#pragma unroll
            for (int r = 0; r < 8; r++) {
                uint32_t v = __shfl_up_sync(0xffffffffu, wi[r], off);
                if (lane >= off) wi[r] += v;
            }
        }
#pragma unroll
        for (int r = 0; r < 8; r++) wsum[lane][r] = wi[r] - w0[r];
        if (lane == 31)
#pragma unroll
            for (int r = 0; r < 8; r++) {
                totS[2 * r]     = (int)(wi[r] & 0xFFFFu);
                totS[2 * r + 1] = (int)(wi[r] >> 16);
            }
    }
    __syncthreads();

    if (tid == 0) {
        int b = 0;
        for (int e = 0; e < E_NUM; e++) {
            int k0 = min(totS[e], CAP);
            int k1 = min(totS[8 + e], CAP);
            sbase[e]     = b;
            sbase[8 + e] = b + k0;
            g_cnt[e]  = k0 + k1;
            g_base[e] = b;
            b += k0 + k1;
        }
        g_total = b;
    }

    unsigned short* myex = ex16s + tid * 16;
#pragma unroll
    for (int r = 0; r < 8; r++) {
        uint32_t exv = wsum[warp][r] + inc[r] - pc[r];
        myex[2 * r]     = (unsigned short)(exv & 0xFFFFu);
        myex[2 * r + 1] = (unsigned short)(exv >> 16);
    }
    __syncthreads();

    const float2* gw = (const float2*)g_topk_w;
#pragma unroll
    for (int i = 0; i < 8; i++) {
        int t = tid * 8 + i;
        float2 wts = gw[t];
        int s0 = idx[i].x;
        int s1 = 8 + idx[i].y;
        int r0 = myex[s0]++;
        if (r0 < CAP) { int p = sbase[s0] + r0; g_tok[p] = t; g_wt[p] = wts.x; }
        int r1 = myex[s1]++;
        if (r1 < CAP) { int p = sbase[s1] + r1; g_tok[p] = t; g_wt[p] = wts.y; }
    }
}

// ---------------------------------------------------------------------------
// Compact: 2 independent float4 gathers per thread (MLP=2).
// ---------------------------------------------------------------------------
__global__ __launch_bounds__(256) void compact_kernel(const float* __restrict__ x)
{
    const int NQ = MAXR_PAD * (D_DIM / 4);
    int i0 = blockIdx.x * 512 + threadIdx.x;
#pragma unroll
    for (int u = 0; u < 2; u++) {
        int i = i0 + u * 256;
        if (i >= NQ) return;
        int row = i / (D_DIM / 4), c4 = i % (D_DIM / 4);
        float4 v = make_float4(0.f, 0.f, 0.f, 0.f);
        if (row < g_total) {
            int tok = g_tok[row];
            v = ((const float4*)(x + (size_t)tok * D_DIM))[c4];
        }
        *(uint2*)(g_Ah + (size_t)row * D_DIM + c4 * 4) =
            make_uint2(pack2h(__float2half_rn(v.x), __float2half_rn(v.y)),
                       pack2h(__float2half_rn(v.z), __float2half_rn(v.w)));
    }
}

// ---------------------------------------------------------------------------
// FFN1: CTA 128m x (64 gate + 64 up), K=768. 8 warps: wm (2x64 rows),
// wn (4x16 cols). acc 64 floats/thread. 3-stage cp.async; 2 CTAs/SM.
// Grid z == E_NUM: heterogeneous blocks converting Wo fp32->fp16 instead
// (overlaps with the tensor-bound GEMM blocks; done before ffn2 launches).
// ---------------------------------------------------------------------------
__global__ __launch_bounds__(256, 2) void ffn1_mma(const float* __restrict__ wo, int n4)
{
    extern __shared__ __align__(16) char dsm[];
    __shared__ float wts_sh[128];

    if (blockIdx.z == E_NUM) {
        // ---- Wo conversion role -----------------------------------------
        int rank = blockIdx.y * gridDim.x + blockIdx.x;   // 0 .. 1919
        const int stride = 48 * 40 * 256;
        for (int i = rank * 256 + threadIdx.x; i < n4; i += stride) {
            float4 v = ((const float4*)wo)[i];
            uint2 ph = make_uint2(pack2h(__float2half_rn(v.x), __float2half_rn(v.y)),
                                  pack2h(__float2half_rn(v.z), __float2half_rn(v.w)));
            *(uint2*)(g_Woh + (size_t)i * 4) = ph;
        }
        return;
    }

    int e   = blockIdx.z;
    int cnt = g_cnt[e];
    int m0  = blockIdx.y * 128;
    if (m0 >= cnt) return;
    int n0   = blockIdx.x * 64;
    int base = g_base[e];

    int tid = threadIdx.x, lane = tid & 31, wid = tid >> 5;
    int gid = lane >> 2, tig = lane & 3;
    int wm = wid & 1, wn = wid >> 1;

    if (tid < 128) {
        int m = m0 + tid;
        wts_sh[tid] = (m < cnt) ? g_wt[base + m] : 0.f;
    }

    const __half* pA = g_Ah  + (size_t)(base + m0) * D_DIM;
    const __half* pG = g_Wgh + (size_t)(e * F_DIM + n0) * D_DIM;
    const __half* pU = g_Wuh + (size_t)(e * F_DIM + n0) * D_DIM;
    uint32_t sb = smem_u32(dsm);

    uint32_t aoff = (uint32_t)((lane & 15) * STR + ((lane >> 4) << 4));
    uint32_t boff = (uint32_t)(((lane & 7) + ((lane >> 4) << 3)) * STR + (((lane >> 3) & 1) << 4));
    uint32_t aRow = (uint32_t)(wm * 64) * STR;
    uint32_t bRow = (uint32_t)(wn * 16) * STR;

    float accg[4][2][4], accu[4][2][4];
#pragma unroll
    for (int mt = 0; mt < 4; mt++)
#pragma unroll
        for (int nt = 0; nt < 2; nt++)
#pragma unroll
            for (int r = 0; r < 4; r++) { accg[mt][nt][r] = 0.f; accu[mt][nt][r] = 0.f; }

    const int NCH = D_DIM / 32;   // 24
    stage_load1(sb + 0 * STG1, tid, pA, pG, pU, 0);
    stage_load1(sb + 1 * STG1, tid, pA, pG, pU, 32);

    for (int ch = 0; ch < NCH; ch++) {
        if (ch + 1 < NCH) { CPWAIT(1); } else { CPWAIT(0); }
        __syncthreads();
        if (ch + 2 < NCH)
            stage_load1(sb + ((ch + 2) % 3) * STG1, tid, pA, pG, pU, (ch + 2) * 32);

        uint32_t s0 = sb + (ch % 3) * STG1;
#pragma unroll
        for (int ks = 0; ks < 2; ks++) {
            uint32_t cb = ks * 32;
            uint32_t ah[4][4], bg[2][2], bu[2][2];
#pragma unroll
            for (int mt = 0; mt < 4; mt++)
                LDSM4(ah[mt][0], ah[mt][1], ah[mt][2], ah[mt][3],
                      s0 + aRow + (uint32_t)(mt * 16) * STR + cb + aoff);
            LDSM4(bg[0][0], bg[0][1], bg[1][0], bg[1][1],
                  s0 + MATB + bRow + cb + boff);
            LDSM4(bu[0][0], bu[0][1], bu[1][0], bu[1][1],
                  s0 + MATB + HMATB + bRow + cb + boff);
#pragma unroll
            for (int mt = 0; mt < 4; mt++)
#pragma unroll
                for (int nt = 0; nt < 2; nt++) {
                    MMAH(accg[mt][nt], ah[mt], bg[nt]);
                    MMAH(accu[mt][nt], ah[mt], bu[nt]);
                }
        }
    }

    // epilogue: h = silu(g)*u*wt -> fp16
#pragma unroll
    for (int mt = 0; mt < 4; mt++)
#pragma unroll
        for (int nt = 0; nt < 2; nt++) {
            int c0 = wn * 16 + nt * 8 + tig * 2;
#pragma unroll
            for (int half = 0; half < 2; half++) {
                int r = wm * 64 + mt * 16 + gid + half * 8;
                if (m0 + r < cnt) {
                    float wt = wts_sh[r];
                    float g0 = accg[mt][nt][half * 2 + 0];
                    float g1 = accg[mt][nt][half * 2 + 1];
                    float u0 = accu[mt][nt][half * 2 + 0];
                    float u1 = accu[mt][nt][half * 2 + 1];
                    float h0 = silu_f(g0) * u0 * wt;
                    float h1 = silu_f(g1) * u1 * wt;
                    size_t off = (size_t)(base + m0 + r) * F_DIM + n0 + c0;
                    *(uint32_t*)(g_Hh + off) =
                        pack2h(__float2half_rn(h0), __float2half_rn(h1));
                }
            }
        }
}

// ---------------------------------------------------------------------------
// FFN2: CTA 128x128, K=3072. mats: 0=Hh 1=Bh. 2 CTAs/SM, 3-stage pipeline.
// Packed red.global.add.v2.f32 epilogue.
// ---------------------------------------------------------------------------
__global__ __launch_bounds__(256, 2) void ffn2_mma(float* __restrict__ out)
{
    extern __shared__ __align__(16) char dsm[];
    __shared__ int toks_sh[128];

    int e   = blockIdx.z;
    int cnt = g_cnt[e];
    int m0  = blockIdx.y * 128;
    if (m0 >= cnt) return;
    int n0   = blockIdx.x * 128;
    int base = g_base[e];

    int tid = threadIdx.x, lane = tid & 31, wid = tid >> 5;
    int gid = lane >> 2, tig = lane & 3;
    int wm = wid >> 2, wn = wid & 3;

    if (tid < 128) {
        int m = m0 + tid;
        toks_sh[tid] = (m < cnt) ? g_tok[base + m] : 0;
    }

    const __half* pA = g_Hh  + (size_t)(base + m0) * F_DIM;
    const __half* pB = g_Woh + (size_t)(e * D_DIM + n0) * F_DIM;
    uint32_t sb = smem_u32(dsm);

    uint32_t aoff = (uint32_t)((lane & 15) * STR + ((lane >> 4) << 4));
    uint32_t boff = (uint32_t)(((lane & 7) + ((lane >> 4) << 3)) * STR + (((lane >> 3) & 1) << 4));
    uint32_t aRow = (uint32_t)(wm * 64) * STR;
    uint32_t bRow = (uint32_t)(wn * 32) * STR;

    float acc[4][4][4];
#pragma unroll
    for (int mt = 0; mt < 4; mt++)
#pragma unroll
        for (int nt = 0; nt < 4; nt++)
#pragma unroll
            for (int r = 0; r < 4; r++) acc[mt][nt][r] = 0.f;

    const int NCH = F_DIM / 32;   // 96
    stage_load2(sb + 0 * STG2, tid, pA, pB, 0,  F_DIM);
    stage_load2(sb + 1 * STG2, tid, pA, pB, 32, F_DIM);

    for (int ch = 0; ch < NCH; ch++) {
        if (ch + 1 < NCH) { CPWAIT(1); } else { CPWAIT(0); }
        __syncthreads();
        if (ch + 2 < NCH)
            stage_load2(sb + ((ch + 2) % 3) * STG2, tid, pA, pB, (ch + 2) * 32, F_DIM);

        uint32_t s0 = sb + (ch % 3) * STG2;
#pragma unroll
        for (int ks = 0; ks < 2; ks++) {
            uint32_t cb = ks * 32;
            uint32_t ah[4][4], bh[4][2];
#pragma unroll
            for (int mt = 0; mt < 4; mt++)
                LDSM4(ah[mt][0], ah[mt][1], ah[mt][2], ah[mt][3],
                      s0 + aRow + (uint32_t)(mt * 16) * STR + cb + aoff);
#pragma unroll
            for (int np = 0; np < 2; np++)
                LDSM4(bh[np*2][0], bh[np*2][1], bh[np*2+1][0], bh[np*2+1][1],
                      s0 + MATB + bRow + (uint32_t)(np * 16) * STR + cb + boff);
#pragma unroll
            for (int mt = 0; mt < 4; mt++)
#pragma unroll
                for (int nt = 0; nt < 4; nt++)
                    MMAH(acc[mt][nt], ah[mt], bh[nt]);
        }
    }

    // epilogue: packed float2 reduction into out[tok]
#pragma unroll
    for (int mt = 0; mt < 4; mt++)
#pragma unroll
        for (int nt = 0; nt < 4; nt++) {
            int c0 = wn * 32 + nt * 8 + tig * 2;
#pragma unroll
            for (int half = 0; half < 2; half++) {
                int r = wm * 64 + mt * 16 + gid + half * 8;
                if (m0 + r < cnt) {
                    int tok = toks_sh[r];
                    float* orow = out + (size_t)tok * D_DIM + n0 + c0;
                    red2(orow, acc[mt][nt][half * 2 + 0], acc[mt][nt][half * 2 + 1]);
                }
            }
        }
}

// ---------------------------------------------------------------------------
__global__ void aux_kernel(float* __restrict__ out, int out_size)
{
    if (threadIdx.x == 0) {
        float lb = 0.f;
        for (int e = 0; e < E_NUM; e++)
            lb += (g_f[e] / (float)(T_TOK * 2)) * (g_P[e] / (float)T_TOK);
        float aux = 0.01f * (float)E_NUM * lb + 0.001f * (g_z / (float)T_TOK);
        if (out_size > T_TOK * D_DIM)
            out[T_TOK * D_DIM] = aux;
    }
}

// ---------------------------------------------------------------------------
extern "C" void kernel_launch(void* const* d_in, const int* in_sizes, int n_in,
                              void* d_out, int out_size)
{
    const float* x       = (const float*)d_in[0];
    const float* w_gate  = (const float*)d_in[1];
    const float* wi_gate = (const float*)d_in[2];
    const float* wi_up   = (const float*)d_in[3];
    const float* wo      = (const float*)d_in[4];
    float* out = (float*)d_out;

    const int SMEM1 = 3 * STG1;   // 61440
    const int SMEM2 = 3 * STG2;   // 61440
    cudaFuncSetAttribute(ffn1_mma, cudaFuncAttributeMaxDynamicSharedMemorySize, SMEM1);
    cudaFuncSetAttribute(ffn2_mma, cudaFuncAttributeMaxDynamicSharedMemorySize, SMEM2);

    cudaMemsetAsync(d_out, 0, (size_t)out_size * sizeof(float));
    init_kernel<<<1, 32>>>();

    int n4w = E_NUM * F_DIM * D_DIM / 4;
    router_conv_kernel<<<16384, 128>>>(x, w_gate, wi_gate, wi_up, n4w);

    scan_kernel<<<1, 1024>>>();

    int nC = MAXR_PAD * (D_DIM / 4);
    compact_kernel<<<(nC + 511) / 512, 256>>>(x);

    ffn1_mma<<<dim3(F_DIM / 64, 2 * CAP / 128, E_NUM + 1), 256, SMEM1>>>(wo, n4w);
    ffn2_mma<<<dim3(D_DIM / 128, 2 * CAP / 128, E_NUM), 256, SMEM2>>>(out);
    aux_kernel<<<1, 32>>>(out, out_size);
}

// round 17
// speedup vs baseline: 1.0117x; 1.0117x over previous
#include <cuda_runtime.h>
#include <cuda_fp16.h>
#include <cstdint>

// ---------------------------------------------------------------------------
// MoE forward, Round 16: R14 topology (fused router + ALL-3-weights convert
// kernel, fp16 single-term HMMA GEMMs, ffn1 128x(64+64), ffn2 128x128,
// 3-stage BK=32 cp.async, 2 CTAs/SM, parallel scan, red.v2 epilogue)
// + R15's improved compact kernel (2 float4/thread).
// ---------------------------------------------------------------------------

#define T_TOK   8192
#define D_DIM   768
#define F_DIM   3072
#define E_NUM   8
#define CAP     2560
#define MAXROWS 16384
#define MAXR_PAD 16512

// ---- device scratch -------------------------------------------------------
__device__ int   g_topk_idx[T_TOK * 2];
__device__ float g_topk_w  [T_TOK * 2];
__device__ int   g_tok [MAXROWS];
__device__ float g_wt  [MAXROWS];
__device__ int   g_cnt [E_NUM];
__device__ int   g_base[E_NUM];
__device__ int   g_total;
__device__ float g_P   [E_NUM];
__device__ float g_f   [E_NUM];
__device__ float g_z;

__device__ __half g_Ah [(size_t)MAXR_PAD * D_DIM];
__device__ __half g_Wgh[(size_t)E_NUM * F_DIM * D_DIM];
__device__ __half g_Wuh[(size_t)E_NUM * F_DIM * D_DIM];
__device__ __half g_Woh[(size_t)E_NUM * D_DIM * F_DIM];
__device__ __half g_Hh [(size_t)MAXR_PAD * F_DIM];

// ---- helpers --------------------------------------------------------------
__device__ __forceinline__ uint32_t smem_u32(const void* p) {
    uint32_t a;
    asm("{ .reg .u64 t; cvta.to.shared.u64 t, %1; cvt.u32.u64 %0, t; }"
        : "=r"(a) : "l"(p));
    return a;
}
__device__ __forceinline__ uint32_t pack2h(__half a, __half b) {
    return (uint32_t)__half_as_ushort(a) | ((uint32_t)__half_as_ushort(b) << 16);
}
__device__ __forceinline__ float silu_f(float g) {
    return g / (1.f + __expf(-g));
}
__device__ __forceinline__ void red2(float* p, float a, float b) {
    asm volatile("red.global.add.v2.f32 [%0], {%1, %2};"
                 :: "l"(p), "f"(a), "f"(b) : "memory");
}

#define CP16(d, s)  asm volatile("cp.async.cg.shared.global [%0], [%1], 16;" :: "r"(d), "l"(s))
#define CPCOMMIT()  asm volatile("cp.async.commit_group;" ::: "memory")
#define CPWAIT(n)   asm volatile("cp.async.wait_group %0;" :: "n"(n) : "memory")

#define MMAH(d, a, b)                                                           \
    asm volatile("mma.sync.aligned.m16n8k16.row.col.f32.f16.f16.f32 "          \
        "{%0,%1,%2,%3}, {%4,%5,%6,%7}, {%8,%9}, {%0,%1,%2,%3};"                \
        : "+f"((d)[0]), "+f"((d)[1]), "+f"((d)[2]), "+f"((d)[3])               \
        : "r"((a)[0]), "r"((a)[1]), "r"((a)[2]), "r"((a)[3]),                  \
          "r"((b)[0]), "r"((b)[1]))

#define LDSM4(r0, r1, r2, r3, ad)                                               \
    asm volatile("ldmatrix.sync.aligned.m8n8.x4.shared.b16 {%0,%1,%2,%3}, [%4];" \
        : "=r"(r0), "=r"(r1), "=r"(r2), "=r"(r3) : "r"(ad))

#define STR   80                  // smem row stride bytes (32 fp16 + 8 pad)
#define MATB  (128 * STR)         // 10240 B per 128x32 matrix
#define HMATB (64 * STR)          // 5120 B per 64x32 matrix
#define STG1  (MATB + 2 * HMATB)  // 20480 (Ah 128r, Gh 64r, Uh 64r)
#define STG2  (2 * MATB)          // 20480 (Hh, Bh)

// ffn1 stage loader: A 128x32 + G 64x32 + U 64x32
__device__ __forceinline__ void stage_load1(uint32_t s0, int tid,
    const __half* pA, const __half* pG, const __half* pU, int k0)
{
#pragma unroll
    for (int it = 0; it < 4; it++) {
        int idx = tid + it * 256;
        uint32_t d; const __half* s;
        if (idx < 512)      { int r = idx >> 2,        j = idx & 3;
            d = s0 + r * STR + j * 16;          s = pA + (size_t)r * D_DIM + k0 + j * 8; }
        else if (idx < 768) { int q = idx - 512; int r = q >> 2, j = q & 3;
            d = s0 + MATB + r * STR + j * 16;   s = pG + (size_t)r * D_DIM + k0 + j * 8; }
        else                { int q = idx - 768; int r = q >> 2, j = q & 3;
            d = s0 + MATB + HMATB + r * STR + j * 16;
                                                 s = pU + (size_t)r * D_DIM + k0 + j * 8; }
        CP16(d, s);
    }
    CPCOMMIT();
}

// ffn2 stage loader: 2 matrices of 128x32
__device__ __forceinline__ void stage_load2(uint32_t s0, int tid,
    const __half* pA, const __half* pB, int k0, int rs)
{
#pragma unroll
    for (int it = 0; it < 4; it++) {
        int idx = tid + it * 256;
        uint32_t d; const __half* s;
        if (idx < 512) { int r = idx >> 2, j = idx & 3;
            d = s0 + r * STR + j * 16;        s = pA + (size_t)r * rs + k0 + j * 8; }
        else           { int q = idx - 512; int r = q >> 2, j = q & 3;
            d = s0 + MATB + r * STR + j * 16; s = pB + (size_t)r * rs + k0 + j * 8; }
        CP16(d, s);
    }
    CPCOMMIT();
}

// ---------------------------------------------------------------------------
__global__ void init_kernel() {
    int t = threadIdx.x;
    if (t < E_NUM) { g_P[t] = 0.f; g_f[t] = 0.f; }
    if (t == 0) g_z = 0.f;
}

// ---------------------------------------------------------------------------
// Fused router + weight-convert kernel. Grid 16384 x 128 threads.
// Blocks with (bid & 7) == 0 (2048): router for 4 tokens. Other 14336
// blocks: grid-stride fp32->fp16 conversion of all 3 weight tensors.
// ---------------------------------------------------------------------------
__global__ __launch_bounds__(128) void router_conv_kernel(
    const float* __restrict__ x, const float* __restrict__ w_gate,
    const float* __restrict__ wg, const float* __restrict__ wu,
    const float* __restrict__ wo, int n4)
{
    int bid = blockIdx.x;

    if ((bid & 7) == 0) {
        // ---- router role -------------------------------------------------
        int warp = threadIdx.x >> 5, lane = threadIdx.x & 31;
        int t = (bid >> 3) * 4 + warp;
        if (t >= T_TOK) return;

        const float* xr = x + (size_t)t * D_DIM;
        float a[24];
#pragma unroll
        for (int i = 0; i < 24; i++) a[i] = xr[i * 32 + lane];

        float logits[E_NUM];
#pragma unroll
        for (int e = 0; e < E_NUM; e++) {
            const float* w = w_gate + (size_t)e * D_DIM;
            float s = 0.f;
#pragma unroll
            for (int i = 0; i < 24; i++) s += a[i] * w[i * 32 + lane];
#pragma unroll
            for (int o = 16; o; o >>= 1) s += __shfl_xor_sync(0xffffffffu, s, o);
            logits[e] = s;
        }

        if (lane == 0) {
            float mx = logits[0];
#pragma unroll
            for (int e = 1; e < E_NUM; e++) mx = fmaxf(mx, logits[e]);
            float pe[E_NUM], se = 0.f;
#pragma unroll
            for (int e = 0; e < E_NUM; e++) { pe[e] = expf(logits[e] - mx); se += pe[e]; }
            float inv = 1.f / se;

            int i0 = 0; float p0 = pe[0];
#pragma unroll
            for (int e = 1; e < E_NUM; e++) if (pe[e] > p0) { p0 = pe[e]; i0 = e; }
            int i1 = -1; float p1 = -1.f;
#pragma unroll
            for (int e = 0; e < E_NUM; e++) if (e != i0 && pe[e] > p1) { p1 = pe[e]; i1 = e; }

            float q0 = p0 * inv, q1 = p1 * inv;
            float sn = 1.f / (q0 + q1);
            g_topk_idx[t * 2 + 0] = i0;
            g_topk_idx[t * 2 + 1] = i1;
            g_topk_w  [t * 2 + 0] = q0 * sn;
            g_topk_w  [t * 2 + 1] = q1 * sn;

            float lse = mx + logf(se);
            atomicAdd(&g_z, lse * lse);
#pragma unroll
            for (int e = 0; e < E_NUM; e++) atomicAdd(&g_P[e], pe[e] * inv);
            atomicAdd(&g_f[i0], 1.f);
            atomicAdd(&g_f[i1], 1.f);
        }
    } else {
        // ---- weight conversion role -------------------------------------
        int crank = bid - (bid >> 3) - 1;              // 0 .. 14335
        const int total  = 3 * n4;
        const int stride = 14336 * 128;
        for (int i = crank * 128 + threadIdx.x; i < total; i += stride) {
            const float* src;
            __half* dst;
            int j = i;
            if (i < n4)            { src = wg; dst = g_Wgh; }
            else if (i < 2 * n4)   { src = wu; dst = g_Wuh; j = i - n4; }
            else                   { src = wo; dst = g_Woh; j = i - 2 * n4; }
            float4 v = ((const float4*)src)[j];
            uint2 ph = make_uint2(pack2h(__float2half_rn(v.x), __float2half_rn(v.y)),
                                  pack2h(__float2half_rn(v.z), __float2half_rn(v.w)));
            *(uint2*)(dst + (size_t)j * 4) = ph;
        }
    }
}

// ---------------------------------------------------------------------------
// Block-parallel dispatch scan (1024 thr, packed 16-stream prefix sum).
// ---------------------------------------------------------------------------
__global__ __launch_bounds__(1024) void scan_kernel()
{
    __shared__ uint32_t wsum[32][8];
    __shared__ unsigned short ex16s[1024 * 16];   // 32 KB
    __shared__ int sbase[16];
    __shared__ int totS[16];

    int tid = threadIdx.x, lane = tid & 31, warp = tid >> 5;

    const int2* gidx = (const int2*)g_topk_idx;
    int2 idx[8];
    unsigned long long c4 = 0ull;
#pragma unroll
    for (int i = 0; i < 8; i++) {
        idx[i] = gidx[tid * 8 + i];
        c4 += 1ull << (idx[i].x * 4);
        c4 += 1ull << ((8 + idx[i].y) * 4);
    }

    uint32_t pc[8], inc[8];
#pragma unroll
    for (int r = 0; r < 8; r++) {
        uint32_t lo = (uint32_t)((c4 >> (r * 8)) & 0xF);
        uint32_t hi = (uint32_t)((c4 >> (r * 8 + 4)) & 0xF);
        pc[r] = lo | (hi << 16);
        inc[r] = pc[r];
    }

    for (int off = 1; off < 32; off <<= 1) {
#pragma unroll
        for (int r = 0; r < 8; r++) {
            uint32_t v = __shfl_up_sync(0xffffffffu, inc[r], off);
            if (lane >= off) inc[r] += v;
        }
    }
    if (lane == 31)
#pragma unroll
        for (int r = 0; r < 8; r++) wsum[warp][r] = inc[r];
    __syncthreads();

    if (warp == 0) {
        uint32_t w0[8], wi[8];
#pragma unroll
        for (int r = 0; r < 8; r++) { w0[r] = wsum[lane][r]; wi[r] = w0[r]; }
        for (int off = 1; off < 32; off <<= 1) {
#pragma unroll
            for (int r = 0; r < 8; r++) {
                uint32_t v = __shfl_up_sync(0xffffffffu, wi[r], off);
                if (lane >= off) wi[r] += v;
            }
        }
#pragma unroll
        for (int r = 0; r < 8; r++) wsum[lane][r] = wi[r] - w0[r];
        if (lane == 31)
#pragma unroll
            for (int r = 0; r < 8; r++) {
                totS[2 * r]     = (int)(wi[r] & 0xFFFFu);
                totS[2 * r + 1] = (int)(wi[r] >> 16);
            }
    }
    __syncthreads();

    if (tid == 0) {
        int b = 0;
        for (int e = 0; e < E_NUM; e++) {
            int k0 = min(totS[e], CAP);
            int k1 = min(totS[8 + e], CAP);
            sbase[e]     = b;
            sbase[8 + e] = b + k0;
            g_cnt[e]  = k0 + k1;
            g_base[e] = b;
            b += k0 + k1;
        }
        g_total = b;
    }

    unsigned short* myex = ex16s + tid * 16;
#pragma unroll
    for (int r = 0; r < 8; r++) {
        uint32_t exv = wsum[warp][r] + inc[r] - pc[r];
        myex[2 * r]     = (unsigned short)(exv & 0xFFFFu);
        myex[2 * r + 1] = (unsigned short)(exv >> 16);
    }
    __syncthreads();

    const float2* gw = (const float2*)g_topk_w;
#pragma unroll
    for (int i = 0; i < 8; i++) {
        int t = tid * 8 + i;
        float2 wts = gw[t];
        int s0 = idx[i].x;
        int s1 = 8 + idx[i].y;
        int r0 = myex[s0]++;
        if (r0 < CAP) { int p = sbase[s0] + r0; g_tok[p] = t; g_wt[p] = wts.x; }
        int r1 = myex[s1]++;
        if (r1 < CAP) { int p = sbase[s1] + r1; g_tok[p] = t; g_wt[p] = wts.y; }
    }
}

// ---------------------------------------------------------------------------
// Compact: 2 independent float4 gathers per thread (MLP=2).
// ---------------------------------------------------------------------------
__global__ __launch_bounds__(256) void compact_kernel(const float* __restrict__ x)
{
    const int NQ = MAXR_PAD * (D_DIM / 4);
    int i0 = blockIdx.x * 512 + threadIdx.x;
#pragma unroll
    for (int u = 0; u < 2; u++) {
        int i = i0 + u * 256;
        if (i >= NQ) return;
        int row = i / (D_DIM / 4), c4 = i % (D_DIM / 4);
        float4 v = make_float4(0.f, 0.f, 0.f, 0.f);
        if (row < g_total) {
            int tok = g_tok[row];
            v = ((const float4*)(x + (size_t)tok * D_DIM))[c4];
        }
        *(uint2*)(g_Ah + (size_t)row * D_DIM + c4 * 4) =
            make_uint2(pack2h(__float2half_rn(v.x), __float2half_rn(v.y)),
                       pack2h(__float2half_rn(v.z), __float2half_rn(v.w)));
    }
}

// ---------------------------------------------------------------------------
// FFN1: CTA 128m x (64 gate + 64 up), K=768. 8 warps: wm (2x64 rows),
// wn (4x16 cols). acc 64 floats/thread. 3-stage cp.async; 2 CTAs/SM.
// ---------------------------------------------------------------------------
__global__ __launch_bounds__(256, 2) void ffn1_mma()
{
    extern __shared__ __align__(16) char dsm[];
    __shared__ float wts_sh[128];

    int e   = blockIdx.z;
    int cnt = g_cnt[e];
    int m0  = blockIdx.y * 128;
    if (m0 >= cnt) return;
    int n0   = blockIdx.x * 64;
    int base = g_base[e];

    int tid = threadIdx.x, lane = tid & 31, wid = tid >> 5;
    int gid = lane >> 2, tig = lane & 3;
    int wm = wid & 1, wn = wid >> 1;

    if (tid < 128) {
        int m = m0 + tid;
        wts_sh[tid] = (m < cnt) ? g_wt[base + m] : 0.f;
    }

    const __half* pA = g_Ah  + (size_t)(base + m0) * D_DIM;
    const __half* pG = g_Wgh + (size_t)(e * F_DIM + n0) * D_DIM;
    const __half* pU = g_Wuh + (size_t)(e * F_DIM + n0) * D_DIM;
    uint32_t sb = smem_u32(dsm);

    uint32_t aoff = (uint32_t)((lane & 15) * STR + ((lane >> 4) << 4));
    uint32_t boff = (uint32_t)(((lane & 7) + ((lane >> 4) << 3)) * STR + (((lane >> 3) & 1) << 4));
    uint32_t aRow = (uint32_t)(wm * 64) * STR;
    uint32_t bRow = (uint32_t)(wn * 16) * STR;

    float accg[4][2][4], accu[4][2][4];
#pragma unroll
    for (int mt = 0; mt < 4; mt++)
#pragma unroll
        for (int nt = 0; nt < 2; nt++)
#pragma unroll
            for (int r = 0; r < 4; r++) { accg[mt][nt][r] = 0.f; accu[mt][nt][r] = 0.f; }

    const int NCH = D_DIM / 32;   // 24
    stage_load1(sb + 0 * STG1, tid, pA, pG, pU, 0);
    stage_load1(sb + 1 * STG1, tid, pA, pG, pU, 32);

    for (int ch = 0; ch < NCH; ch++) {
        if (ch + 1 < NCH) { CPWAIT(1); } else { CPWAIT(0); }
        __syncthreads();
        if (ch + 2 < NCH)
            stage_load1(sb + ((ch + 2) % 3) * STG1, tid, pA, pG, pU, (ch + 2) * 32);

        uint32_t s0 = sb + (ch % 3) * STG1;
#pragma unroll
        for (int ks = 0; ks < 2; ks++) {
            uint32_t cb = ks * 32;
            uint32_t ah[4][4], bg[2][2], bu[2][2];
#pragma unroll
            for (int mt = 0; mt < 4; mt++)
                LDSM4(ah[mt][0], ah[mt][1], ah[mt][2], ah[mt][3],
                      s0 + aRow + (uint32_t)(mt * 16) * STR + cb + aoff);
            LDSM4(bg[0][0], bg[0][1], bg[1][0], bg[1][1],
                  s0 + MATB + bRow + cb + boff);
            LDSM4(bu[0][0], bu[0][1], bu[1][0], bu[1][1],
                  s0 + MATB + HMATB + bRow + cb + boff);
#pragma unroll
            for (int mt = 0; mt < 4; mt++)
#pragma unroll
                for (int nt = 0; nt < 2; nt++) {
                    MMAH(accg[mt][nt], ah[mt], bg[nt]);
                    MMAH(accu[mt][nt], ah[mt], bu[nt]);
                }
        }
    }

    // epilogue: h = silu(g)*u*wt -> fp16
#pragma unroll
    for (int mt = 0; mt < 4; mt++)
#pragma unroll
        for (int nt = 0; nt < 2; nt++) {
            int c0 = wn * 16 + nt * 8 + tig * 2;
#pragma unroll
            for (int half = 0; half < 2; half++) {
                int r = wm * 64 + mt * 16 + gid + half * 8;
                if (m0 + r < cnt) {
                    float wt = wts_sh[r];
                    float g0 = accg[mt][nt][half * 2 + 0];
                    float g1 = accg[mt][nt][half * 2 + 1];
                    float u0 = accu[mt][nt][half * 2 + 0];
                    float u1 = accu[mt][nt][half * 2 + 1];
                    float h0 = silu_f(g0) * u0 * wt;
                    float h1 = silu_f(g1) * u1 * wt;
                    size_t off = (size_t)(base + m0 + r) * F_DIM + n0 + c0;
                    *(uint32_t*)(g_Hh + off) =
                        pack2h(__float2half_rn(h0), __float2half_rn(h1));
                }
            }
        }
}

// ---------------------------------------------------------------------------
// FFN2: CTA 128x128, K=3072. mats: 0=Hh 1=Bh. 2 CTAs/SM, 3-stage pipeline.
// Packed red.global.add.v2.f32 epilogue.
// ---------------------------------------------------------------------------
__global__ __launch_bounds__(256, 2) void ffn2_mma(float* __restrict__ out)
{
    extern __shared__ __align__(16) char dsm[];
    __shared__ int toks_sh[128];

    int e   = blockIdx.z;
    int cnt = g_cnt[e];
    int m0  = blockIdx.y * 128;
    if (m0 >= cnt) return;
    int n0   = blockIdx.x * 128;
    int base = g_base[e];

    int tid = threadIdx.x, lane = tid & 31, wid = tid >> 5;
    int gid = lane >> 2, tig = lane & 3;
    int wm = wid >> 2, wn = wid & 3;

    if (tid < 128) {
        int m = m0 + tid;
        toks_sh[tid] = (m < cnt) ? g_tok[base + m] : 0;
    }

    const __half* pA = g_Hh  + (size_t)(base + m0) * F_DIM;
    const __half* pB = g_Woh + (size_t)(e * D_DIM + n0) * F_DIM;
    uint32_t sb = smem_u32(dsm);

    uint32_t aoff = (uint32_t)((lane & 15) * STR + ((lane >> 4) << 4));
    uint32_t boff = (uint32_t)(((lane & 7) + ((lane >> 4) << 3)) * STR + (((lane >> 3) & 1) << 4));
    uint32_t aRow = (uint32_t)(wm * 64) * STR;
    uint32_t bRow = (uint32_t)(wn * 32) * STR;

    float acc[4][4][4];
#pragma unroll
    for (int mt = 0; mt < 4; mt++)
#pragma unroll
        for (int nt = 0; nt < 4; nt++)
#pragma unroll
            for (int r = 0; r < 4; r++) acc[mt][nt][r] = 0.f;

    const int NCH = F_DIM / 32;   // 96
    stage_load2(sb + 0 * STG2, tid, pA, pB, 0,  F_DIM);
    stage_load2(sb + 1 * STG2, tid, pA, pB, 32, F_DIM);

    for (int ch = 0; ch < NCH; ch++) {
        if (ch + 1 < NCH) { CPWAIT(1); } else { CPWAIT(0); }
        __syncthreads();
        if (ch + 2 < NCH)
            stage_load2(sb + ((ch + 2) % 3) * STG2, tid, pA, pB, (ch + 2) * 32, F_DIM);

        uint32_t s0 = sb + (ch % 3) * STG2;
#pragma unroll
        for (int ks = 0; ks < 2; ks++) {
            uint32_t cb = ks * 32;
            uint32_t ah[4][4], bh[4][2];
#pragma unroll
            for (int mt = 0; mt < 4; mt++)
                LDSM4(ah[mt][0], ah[mt][1], ah[mt][2], ah[mt][3],
                      s0 + aRow + (uint32_t)(mt * 16) * STR + cb + aoff);
#pragma unroll
            for (int np = 0; np < 2; np++)
                LDSM4(bh[np*2][0], bh[np*2][1], bh[np*2+1][0], bh[np*2+1][1],
                      s0 + MATB + bRow + (uint32_t)(np * 16) * STR + cb + boff);
#pragma unroll
            for (int mt = 0; mt < 4; mt++)
#pragma unroll
                for (int nt = 0; nt < 4; nt++)
                    MMAH(acc[mt][nt], ah[mt], bh[nt]);
        }
    }

    // epilogue: packed float2 reduction into out[tok]
#pragma unroll
    for (int mt = 0; mt < 4; mt++)
#pragma unroll
        for (int nt = 0; nt < 4; nt++) {
            int c0 = wn * 32 + nt * 8 + tig * 2;
#pragma unroll
            for (int half = 0; half < 2; half++) {
                int r = wm * 64 + mt * 16 + gid + half * 8;
                if (m0 + r < cnt) {
                    int tok = toks_sh[r];
                    float* orow = out + (size_t)tok * D_DIM + n0 + c0;
                    red2(orow, acc[mt][nt][half * 2 + 0], acc[mt][nt][half * 2 + 1]);
                }
            }
        }
}

// ---------------------------------------------------------------------------
__global__ void aux_kernel(float* __restrict__ out, int out_size)
{
    if (threadIdx.x == 0) {
        float lb = 0.f;
        for (int e = 0; e < E_NUM; e++)
            lb += (g_f[e] / (float)(T_TOK * 2)) * (g_P[e] / (float)T_TOK);
        float aux = 0.01f * (float)E_NUM * lb + 0.001f * (g_z / (float)T_TOK);
        if (out_size > T_TOK * D_DIM)
            out[T_TOK * D_DIM] = aux;
    }
}

// ---------------------------------------------------------------------------
extern "C" void kernel_launch(void* const* d_in, const int* in_sizes, int n_in,
                              void* d_out, int out_size)
{
    const float* x       = (const float*)d_in[0];
    const float* w_gate  = (const float*)d_in[1];
    const float* wi_gate = (const float*)d_in[2];
    const float* wi_up   = (const float*)d_in[3];
    const float* wo      = (const float*)d_in[4];
    float* out = (float*)d_out;

    const int SMEM1 = 3 * STG1;   // 61440
    const int SMEM2 = 3 * STG2;   // 61440
    cudaFuncSetAttribute(ffn1_mma, cudaFuncAttributeMaxDynamicSharedMemorySize, SMEM1);
    cudaFuncSetAttribute(ffn2_mma, cudaFuncAttributeMaxDynamicSharedMemorySize, SMEM2);

    cudaMemsetAsync(d_out, 0, (size_t)out_size * sizeof(float));
    init_kernel<<<1, 32>>>();

    int n4w = E_NUM * F_DIM * D_DIM / 4;
    router_conv_kernel<<<16384, 128>>>(x, w_gate, wi_gate, wi_up, wo, n4w);

    scan_kernel<<<1, 1024>>>();

    int nC = MAXR_PAD * (D_DIM / 4);
    compact_kernel<<<(nC + 511) / 512, 256>>>(x);

    ffn1_mma<<<dim3(F_DIM / 64, 2 * CAP / 128, E_NUM), 256, SMEM1>>>();
    ffn2_mma<<<dim3(D_DIM / 128, 2 * CAP / 128, E_NUM), 256, SMEM2>>>(out);
    aux_kernel<<<1, 32>>>(out, out_size);
}